// round 17
// baseline (speedup 1.0000x reference)
#include <cuda_runtime.h>
#include <cuda_fp16.h>
#include <cstring>

// PositionalSparseLinear: out[b,o] = sum_k x[b, conn[o,k]] * w[o,k]
//   x: [1024,8192] f32   conn: [8192,32] i32   w: [8192,32] f32   out: [1024,8192] f32
//
// Round 17 (R12 main kernel + cross-output coordinated surplus schedule):
//  - fp16-staged transposed SMEM batch tile (BT=8 per 16B col) [R4]
//  - R11 slot targeting for rank<4 entries (8 lanes of a warp-quarter hit
//    8 distinct bank groups by construction).
//  - NEW prep: one block per 32 consecutive outputs (= one runtime warp).
//    Surplus entries (rank>=4) are placed into deficit slots COORDINATED
//    across the 32 outputs via a shared occ[quarter][slot] group-mask:
//    each surplus picks a deficit slot where its group is still absent.
//    Removes most surplus-induced conflicts: phases ~4.8 -> ~4.3 (floor 4).
//  - flat chunk split over 148 CTAs, 512 thr x 2 outputs, FFMA2 [R10/R12]

#define IN_F   8192
#define OUT_F  8192
#define KW     32
#define BATCH  1024
#define BT     8
#define THREADS 512
#define N_CTAS 148
#define TOTAL_CHUNKS ((BATCH / BT) * 8)               // 1024
#define SMEM_BYTES (IN_F * BT * (int)sizeof(__half))  // 131072

__device__ unsigned int g_cwT[KW * OUT_F];   // [slot][o] packed (idx<<16)|half(w)

static __device__ __forceinline__ __half2 u32_as_h2(unsigned int u) {
    __half2 h; memcpy(&h, &u, sizeof(h)); return h;
}

// Block = 1024 threads = 32 warps; warp i handles output o_base+i (lane = k).
// Fill slots: entry of group g, rank r<4 -> slot 4*((g-o)&7)+r (target group
// of that slot == g). Surplus entries (r>=4) get deficit slots, coordinated
// across the block's 32 outputs via occ[quarter][slot] so the 8 lanes of a
// runtime warp-quarter carry 8 distinct groups wherever possible.
__global__ __launch_bounds__(1024, 1)
void psl_prep(const int* __restrict__ conn, const float* __restrict__ w)
{
    __shared__ unsigned int occ[4][32];   // [quarter][slot] -> 8-bit group mask

    const int i    = threadIdx.x >> 5;    // output index within group (0..31)
    const int lane = threadIdx.x & 31;    // entry index k / slot index t
    const int o    = blockIdx.x * 32 + i;

    if (threadIdx.x < 128) occ[threadIdx.x >> 5][threadIdx.x & 31] = 0u;
    __syncthreads();

    const int   c  = conn[(size_t)o * KW + lane];
    const float wv = w   [(size_t)o * KW + lane];
    const unsigned short hb = __half_as_ushort(__float2half_rn(wv));
    const unsigned int packed = ((unsigned int)c << 16) | (unsigned int)hb;

    const int g = c & 7;
    const unsigned int lt = (1u << lane) - 1u;

    int cnt[8]; int r = 0;
    #pragma unroll
    for (int gg = 0; gg < 8; gg++) {
        unsigned int m = __ballot_sync(0xffffffffu, g == gg);
        cnt[gg] = __popc(m);
        if (gg == g) r = __popc(m & lt);
    }

    // Slot-lane view: lane also represents slot t.
    const int t  = lane;
    const int dT = ((t >> 2) + o) & 7;            // target group of slot t
    int cntD = 0;
    #pragma unroll
    for (int gg = 0; gg < 8; gg++) if (gg == dT) cntD = cnt[gg];
    const bool fillT = (t & 3) < cntD;            // slot claimed by rank<4 entry
    const unsigned int fillMask    = __ballot_sync(0xffffffffu, fillT);
    const unsigned int deficitMask = ~fillMask;

    int slot = -1;
    if (r < 4) slot = 4 * ((g - o) & 7) + r;      // fill slots (unique by g,r)

    const int q = i >> 3;                          // runtime quarter of this output

    // 8 sequential steps: outputs i with i%8==s across the 4 quarters run in
    // parallel; within a step, each warp assigns its surplus entries.
    for (int s = 0; s < 8; s++) {
        if ((i & 7) == s) {
            unsigned int myoccT = occ[q][t];       // lane t: occupancy of slot t
            unsigned int surplus = __ballot_sync(0xffffffffu, r >= 4);
            unsigned int freeM   = deficitMask;
            while (surplus) {
                const int L  = __ffs(surplus) - 1;
                const int gL = __shfl_sync(0xffffffffu, g, L);
                unsigned int okv =
                    __ballot_sync(0xffffffffu, ((myoccT >> gL) & 1u) == 0u) & freeM;
                const unsigned int pick = okv ? okv : freeM;
                const int t0 = __ffs(pick) - 1;
                if (lane == L)  slot = t0;
                if (lane == t0) myoccT |= (1u << gL);
                freeM   &= ~(1u << t0);
                surplus &= ~(1u << L);
            }
            if (fillT) myoccT |= (1u << dT);       // publish fill groups
            occ[q][t] = myoccT;
        }
        __syncthreads();
    }

    g_cwT[(size_t)slot * OUT_F + o] = packed;
}

__global__ __launch_bounds__(THREADS, 1)
void psl_main(const float* __restrict__ x, float* __restrict__ out)
{
    extern __shared__ uint4 xs[];   // xs[col] = 8 halves: rows b0..b0+7 of col

    const int tid = threadIdx.x;
    const int bid = blockIdx.x;

    const int c_start = (bid * TOTAL_CHUNKS) / N_CTAS;
    const int c_end   = ((bid + 1) * TOTAL_CHUNKS) / N_CTAS;

    int cur_bt = -1;

    #pragma unroll 1
    for (int ch = c_start; ch < c_end; ch++) {
        const int bt = ch >> 3;            // b-tile index
        const int oc = ch & 7;             // output chunk within tile

        if (bt != cur_bt) {
            if (cur_bt >= 0) __syncthreads();   // drain readers of old tile
            const float* xb = x + (size_t)bt * BT * IN_F;
            #pragma unroll
            for (int cc = tid; cc < IN_F; cc += THREADS) {
                float r0 = xb[cc + 0 * (size_t)IN_F];
                float r1 = xb[cc + 1 * (size_t)IN_F];
                float r2 = xb[cc + 2 * (size_t)IN_F];
                float r3 = xb[cc + 3 * (size_t)IN_F];
                float r4 = xb[cc + 4 * (size_t)IN_F];
                float r5 = xb[cc + 5 * (size_t)IN_F];
                float r6 = xb[cc + 6 * (size_t)IN_F];
                float r7 = xb[cc + 7 * (size_t)IN_F];

                __half2 h0 = __floats2half2_rn(r0, r1);
                __half2 h1 = __floats2half2_rn(r2, r3);
                __half2 h2 = __floats2half2_rn(r4, r5);
                __half2 h3 = __floats2half2_rn(r6, r7);

                uint4 v;
                memcpy(&v.x, &h0, 4);
                memcpy(&v.y, &h1, 4);
                memcpy(&v.z, &h2, 4);
                memcpy(&v.w, &h3, 4);
                xs[cc] = v;
            }
            cur_bt = bt;
            __syncthreads();
        }

        // Two outputs per thread: o1 and o1+512. Both preserve o%32==lane.
        const int o1 = oc * 1024 + tid;
        const unsigned int* __restrict__ cwp1 = g_cwT + o1;
        const unsigned int* __restrict__ cwp2 = cwp1 + 512;

        unsigned long long A01 = 0ull, A23 = 0ull, A45 = 0ull, A67 = 0ull;
        unsigned long long B01 = 0ull, B23 = 0ull, B45 = 0ull, B67 = 0ull;

        #pragma unroll 8
        for (int k = 0; k < KW; k++) {
            const unsigned int cw1 = cwp1[(size_t)k * OUT_F];
            const unsigned int cw2 = cwp2[(size_t)k * OUT_F];

            #define PSL_BODY(CW, P01, P23, P45, P67) {                          \
                const int   c_  = (int)((CW) >> 16);                             \
                const float wvf = __half2float(__ushort_as_half(                 \
                                      (unsigned short)((CW) & 0xffffu)));        \
                unsigned long long WV2;                                          \
                asm("mov.b64 %0, {%1, %1};" : "=l"(WV2) : "f"(wvf));             \
                const uint4 hv = xs[c_];                                         \
                float2 f0 = __half22float2(u32_as_h2(hv.x));                     \
                float2 f1 = __half22float2(u32_as_h2(hv.y));                     \
                float2 f2 = __half22float2(u32_as_h2(hv.z));                     \
                float2 f3 = __half22float2(u32_as_h2(hv.w));                     \
                unsigned long long F0, F1, F2, F3;                               \
                asm("mov.b64 %0, {%1, %2};" : "=l"(F0) : "f"(f0.x), "f"(f0.y));  \
                asm("mov.b64 %0, {%1, %2};" : "=l"(F1) : "f"(f1.x), "f"(f1.y));  \
                asm("mov.b64 %0, {%1, %2};" : "=l"(F2) : "f"(f2.x), "f"(f2.y));  \
                asm("mov.b64 %0, {%1, %2};" : "=l"(F3) : "f"(f3.x), "f"(f3.y));  \
                asm("fma.rn.f32x2 %0, %1, %2, %0;" : "+l"(P01) : "l"(F0), "l"(WV2)); \
                asm("fma.rn.f32x2 %0, %1, %2, %0;" : "+l"(P23) : "l"(F1), "l"(WV2)); \
                asm("fma.rn.f32x2 %0, %1, %2, %0;" : "+l"(P45) : "l"(F2), "l"(WV2)); \
                asm("fma.rn.f32x2 %0, %1, %2, %0;" : "+l"(P67) : "l"(F3), "l"(WV2)); \
            }
            PSL_BODY(cw1, A01, A23, A45, A67);
            PSL_BODY(cw2, B01, B23, B45, B67);
            #undef PSL_BODY
        }

        float a0, a1, a2, a3, a4, a5, a6, a7;
        float b0, b1, b2, b3, b4, b5, b6, b7;
        asm("mov.b64 {%0, %1}, %2;" : "=f"(a0), "=f"(a1) : "l"(A01));
        asm("mov.b64 {%0, %1}, %2;" : "=f"(a2), "=f"(a3) : "l"(A23));
        asm("mov.b64 {%0, %1}, %2;" : "=f"(a4), "=f"(a5) : "l"(A45));
        asm("mov.b64 {%0, %1}, %2;" : "=f"(a6), "=f"(a7) : "l"(A67));
        asm("mov.b64 {%0, %1}, %2;" : "=f"(b0), "=f"(b1) : "l"(B01));
        asm("mov.b64 {%0, %1}, %2;" : "=f"(b2), "=f"(b3) : "l"(B23));
        asm("mov.b64 {%0, %1}, %2;" : "=f"(b4), "=f"(b5) : "l"(B45));
        asm("mov.b64 {%0, %1}, %2;" : "=f"(b6), "=f"(b7) : "l"(B67));

        float* op1 = out + (size_t)bt * BT * OUT_F + o1;
        float* op2 = op1 + 512;
        op1[0 * (size_t)OUT_F] = a0;  op2[0 * (size_t)OUT_F] = b0;
        op1[1 * (size_t)OUT_F] = a1;  op2[1 * (size_t)OUT_F] = b1;
        op1[2 * (size_t)OUT_F] = a2;  op2[2 * (size_t)OUT_F] = b2;
        op1[3 * (size_t)OUT_F] = a3;  op2[3 * (size_t)OUT_F] = b3;
        op1[4 * (size_t)OUT_F] = a4;  op2[4 * (size_t)OUT_F] = b4;
        op1[5 * (size_t)OUT_F] = a5;  op2[5 * (size_t)OUT_F] = b5;
        op1[6 * (size_t)OUT_F] = a6;  op2[6 * (size_t)OUT_F] = b6;
        op1[7 * (size_t)OUT_F] = a7;  op2[7 * (size_t)OUT_F] = b7;
    }
}

extern "C" void kernel_launch(void* const* d_in, const int* in_sizes, int n_in,
                              void* d_out, int out_size)
{
    const float* x    = (const float*)d_in[0];   // [1024, 8192] f32
    const int*   conn = (const int*)  d_in[1];   // [8192, 32]   i32
    const float* w    = (const float*)d_in[2];   // [8192, 32]   f32
    float*       out  = (float*)d_out;           // [1024, 8192] f32

    (void)in_sizes; (void)n_in; (void)out_size;

    psl_prep<<<OUT_F / 32, 1024>>>(conn, w);     // 256 blocks

    cudaFuncSetAttribute(psl_main,
                         cudaFuncAttributeMaxDynamicSharedMemorySize,
                         SMEM_BYTES);

    psl_main<<<N_CTAS, THREADS, SMEM_BYTES>>>(x, out);   // 148 CTAs, 1 wave
}